// round 6
// baseline (speedup 1.0000x reference)
#include <cuda_runtime.h>
#include <cuda_fp16.h>
#include <cuda_fp8.h>

#define NN 4096
#define DD 128
#define ITERS 100
#define GRID_SINK 128
#define EPSV 1e-8f
#define MUV (1.0f / 4096.0f)
#define REGC 0.05f
#define VSCALE 1024.0f

// ---------------- static device scratch (allocation-free rule) ----------------
__device__ __align__(256) unsigned char g_K8[3ULL * NN * NN];  // 48 MB fp8 e4m3
__device__ __align__(256) float g_u[3][NN];
__device__ __align__(256) float g_tp[3][4][NN];                // phase-A partials
__device__ __align__(256) float g_sq[3][NN];
__device__ double g_part[3 * GRID_SINK];
__device__ unsigned g_cnt = 0;
__device__ volatile unsigned g_gen = 0;

// ---------------- fp8 helpers --------------------------------------------------
__device__ __forceinline__ unsigned enc4(float a, float b, float c, float d) {
    unsigned short lo = __nv_cvt_float2_to_fp8x2(make_float2(a, b), __NV_SATFINITE, __NV_E4M3);
    unsigned short hi = __nv_cvt_float2_to_fp8x2(make_float2(c, d), __NV_SATFINITE, __NV_E4M3);
    return (unsigned)lo | ((unsigned)hi << 16);
}

__device__ __forceinline__ __half2 dec2h(unsigned short s) {
    __half2_raw r = __nv_cvt_fp8x2_to_halfraw2((__nv_fp8x2_storage_t)s, __NV_E4M3);
    return *reinterpret_cast<__half2*>(&r);
}

// decode 16 fp8 (uint4) -> 8 half2
__device__ __forceinline__ void dec16(uint4 k, __half2* h) {
    h[0] = dec2h((unsigned short)(k.x & 0xFFFFu));
    h[1] = dec2h((unsigned short)(k.x >> 16));
    h[2] = dec2h((unsigned short)(k.y & 0xFFFFu));
    h[3] = dec2h((unsigned short)(k.y >> 16));
    h[4] = dec2h((unsigned short)(k.z & 0xFFFFu));
    h[5] = dec2h((unsigned short)(k.z >> 16));
    h[6] = dec2h((unsigned short)(k.w & 0xFFFFu));
    h[7] = dec2h((unsigned short)(k.w >> 16));
}

__device__ __forceinline__ void dec4f(unsigned x, float* f) {
    float2 a = __half22float2(dec2h((unsigned short)(x & 0xFFFFu)));
    float2 b = __half22float2(dec2h((unsigned short)(x >> 16)));
    f[0] = a.x; f[1] = a.y; f[2] = b.x; f[3] = b.y;
}

// ---------------- grid-wide barrier -------------------------------------------
__device__ __forceinline__ void grid_barrier() {
    __syncthreads();
    if (threadIdx.x == 0) {
        __threadfence();
        unsigned gen = g_gen;
        if (atomicAdd(&g_cnt, 1u) == GRID_SINK - 1) {
            atomicExch(&g_cnt, 0u);
            __threadfence();
            g_gen = gen + 1;
        } else {
            while (g_gen == gen) { }
        }
        __threadfence();   // acquire: CCTL.IVALL flushes L1
    }
    __syncthreads();
}

// ---------------- row squared norms --------------------------------------------
__global__ void rowsq_kernel(const float* __restrict__ z0, const float* __restrict__ z1,
                             const float* __restrict__ z2) {
    int gw = (blockIdx.x * blockDim.x + threadIdx.x) >> 5;
    int lane = threadIdx.x & 31;
    int which = gw >> 12, row = gw & 4095;
    const float* src = which == 0 ? z0 : (which == 1 ? z1 : z2);
    float4 v = *(const float4*)(src + (size_t)row * DD + lane * 4);
    float s = v.x * v.x + v.y * v.y + v.z * v.z + v.w * v.w;
#pragma unroll
    for (int o = 16; o; o >>= 1) s += __shfl_xor_sync(0xffffffffu, s, o);
    if (lane == 0) g_sq[which][row] = s;
}

// ---------------- build K (fp8) for all 3 pairs --------------------------------
__global__ void __launch_bounds__(256) build_kernel(const float* __restrict__ z0,
                                                    const float* __restrict__ z1,
                                                    const float* __restrict__ z2) {
    __shared__ float sx[64][33];
    __shared__ float sy[64][33];
    const int pa[3] = {0, 0, 1};
    const int pb[3] = {1, 2, 2};
    const float* zz[3] = {z0, z1, z2};
    const int p = blockIdx.z;
    const float* x = zz[pa[p]];
    const float* y = zz[pb[p]];

    const int tid = threadIdx.x;
    const int tx = tid & 15, ty = tid >> 4;
    const int row0 = blockIdx.y << 6, col0 = blockIdx.x << 6;

    float acc[4][4] = {};

    for (int kc = 0; kc < DD; kc += 32) {
        __syncthreads();
#pragma unroll
        for (int q = 0; q < 2; q++) {
            int idx = tid + (q << 8);
            int r = idx >> 3, kk = (idx & 7) << 2;
            float4 a = *(const float4*)(x + (size_t)(row0 + r) * DD + kc + kk);
            sx[r][kk] = a.x; sx[r][kk + 1] = a.y; sx[r][kk + 2] = a.z; sx[r][kk + 3] = a.w;
            float4 b = *(const float4*)(y + (size_t)(col0 + r) * DD + kc + kk);
            sy[r][kk] = b.x; sy[r][kk + 1] = b.y; sy[r][kk + 2] = b.z; sy[r][kk + 3] = b.w;
        }
        __syncthreads();
#pragma unroll
        for (int k = 0; k < 32; k++) {
            float xa[4], yb[4];
#pragma unroll
            for (int a = 0; a < 4; a++) xa[a] = sx[ty * 4 + a][k];
#pragma unroll
            for (int b = 0; b < 4; b++) yb[b] = sy[tx * 4 + b][k];
#pragma unroll
            for (int a = 0; a < 4; a++)
#pragma unroll
                for (int b = 0; b < 4; b++)
                    acc[a][b] = fmaf(xa[a], yb[b], acc[a][b]);
        }
    }

    float xs[4], ys[4];
#pragma unroll
    for (int a = 0; a < 4; a++) xs[a] = g_sq[pa[p]][row0 + ty * 4 + a];
#pragma unroll
    for (int b = 0; b < 4; b++) ys[b] = g_sq[pb[p]][col0 + tx * 4 + b];

    const size_t base = (size_t)p * NN * NN;
#pragma unroll
    for (int a = 0; a < 4; a++) {
        size_t off = base + (size_t)(row0 + ty * 4 + a) * NN + col0 + tx * 4;
        float kk[4];
#pragma unroll
        for (int b = 0; b < 4; b++) {
            float c = fmaxf(xs[a] + ys[b] - 2.0f * acc[a][b], 0.0f);
            kk[b] = fmaxf(__expf(-20.0f * c), 0.002f);   // clamp above fp8 underflow
        }
        *(unsigned*)(g_K8 + off) = enc4(kk[0], kk[1], kk[2], kk[3]);
    }
}

// ---------------- persistent fused 3-pair Sinkhorn (fp8 K, half2, 1024 thr) ----
__global__ void __launch_bounds__(1024, 1) sinkhorn_kernel() {
    // phase A: svu[3][1024] half2 (12KB) + red[32][128] float (16KB) = 28KB
    // phase B: svh[3][4096] half (24KB) — overlaps phase-A arrays (barrier-separated)
    __shared__ __align__(16) unsigned char smem_raw[28672];
    __half2* svu = (__half2*)smem_raw;
    float* red = (float*)(smem_raw + 12288);
    __half* svh = (__half*)smem_raw;

    const int c = blockIdx.x;
    const int tid = threadIdx.x;
    const int lane = tid & 31, w = tid >> 5;           // 32 warps
    const int rb = c >> 5, cb = c & 31;                // phase-A tile: 1024r x 128c
    const int cg = lane & 7, ro = lane >> 3;           // col-group(16 cols), row-offset 0..3

    if (tid < 32) {
#pragma unroll
        for (int p = 0; p < 3; p++) g_u[p][c * 32 + tid] = 1.0f;
    }
    grid_barrier();

    for (int it = 0; it < ITERS; it++) {
        // ================= Phase A: partial t = K^T u (all 3 pairs) ===========
#pragma unroll
        for (int p = 0; p < 3; p++)
            svu[p * 1024 + tid] = __float2half2_rn(g_u[p][rb * 1024 + tid]);
        __syncthreads();

#pragma unroll 1
        for (int p = 0; p < 3; p++) {
            // warp w: rows rb*1024 + w*32 .. +32; lane: 16 cols at cg*16, rows ro+4i
            const uint4* Ka = (const uint4*)(g_K8 + (size_t)p * NN * NN +
                                             (size_t)(rb * 1024 + w * 32 + ro) * NN +
                                             cb * 128 + cg * 16);
            const __half2* up = svu + p * 1024 + w * 32 + ro;
            __half2 acc[8];
#pragma unroll
            for (int j = 0; j < 8; j++) acc[j] = __half2half2(__ushort_as_half(0));
#pragma unroll
            for (int i = 0; i < 8; i++) {
                uint4 kr = __ldcg(Ka + (size_t)i * 1024);   // +4 rows
                __half2 uu = up[i * 4];
                __half2 kh[8];
                dec16(kr, kh);
#pragma unroll
                for (int j = 0; j < 8; j++) acc[j] = __hfma2(kh[j], uu, acc[j]);
            }
            float t[16];
#pragma unroll
            for (int j = 0; j < 8; j++) {
                float2 f = __half22float2(acc[j]);
                t[j * 2] = f.x;
                t[j * 2 + 1] = f.y;
            }
            // reduce over ro (lane bits 3,4)
#pragma unroll
            for (int k = 0; k < 16; k++) {
                t[k] += __shfl_xor_sync(0xffffffffu, t[k], 8);
                t[k] += __shfl_xor_sync(0xffffffffu, t[k], 16);
            }
            if (ro == 0) {
#pragma unroll
                for (int k = 0; k < 16; k++) red[w * 128 + cg * 16 + k] = t[k];
            }
            __syncthreads();
            if (tid < 128) {
                float s = red[tid];
#pragma unroll
                for (int w2 = 1; w2 < 32; w2++) s += red[w2 * 128 + tid];
                g_tp[p][rb][cb * 128 + tid] = s;
            }
            __syncthreads();
        }
        grid_barrier();

        // ================= Phase B: u = mu / (K v + eps) ======================
        // stage v'' = VSCALE/(t+eps) as half for all 3 pairs
#pragma unroll 1
        for (int p = 0; p < 3; p++) {
            const float4* tp0 = (const float4*)g_tp[p][0];
            const float4* tp1 = (const float4*)g_tp[p][1];
            const float4* tp2 = (const float4*)g_tp[p][2];
            const float4* tp3 = (const float4*)g_tp[p][3];
            float4 A0 = tp0[tid], A1 = tp1[tid], A2 = tp2[tid], A3 = tp3[tid];
            float4 A = make_float4(A0.x + A1.x + A2.x + A3.x, A0.y + A1.y + A2.y + A3.y,
                                   A0.z + A1.z + A2.z + A3.z, A0.w + A1.w + A2.w + A3.w);
            __half2 h0 = __floats2half2_rn(__fdividef(VSCALE, A.x + EPSV),
                                           __fdividef(VSCALE, A.y + EPSV));
            __half2 h1 = __floats2half2_rn(__fdividef(VSCALE, A.z + EPSV),
                                           __fdividef(VSCALE, A.w + EPSV));
            uint2 pk;
            pk.x = *reinterpret_cast<unsigned*>(&h0);
            pk.y = *reinterpret_cast<unsigned*>(&h1);
            ((uint2*)(svh + p * 4096))[tid] = pk;
        }
        __syncthreads();

#pragma unroll 1
        for (int p = 0; p < 3; p++) {
            const int row = c * 32 + w;   // one row per warp
            const uint4* Kr = (const uint4*)(g_K8 + (size_t)p * NN * NN +
                                             (size_t)row * NN) + lane;
            const uint4* sv4 = (const uint4*)(svh + p * 4096);
            __half2 a0 = __half2half2(__ushort_as_half(0));
            __half2 a1 = a0, a2 = a0, a3 = a0;
#pragma unroll
            for (int i = 0; i < 8; i++) {
                uint4 kr = __ldcg(Kr + i * 32);
                uint4 v0 = sv4[i * 64 + lane * 2];
                uint4 v1 = sv4[i * 64 + lane * 2 + 1];
                __half2 kh[8];
                dec16(kr, kh);
                const __half2* vh0 = (const __half2*)&v0;
                const __half2* vh1 = (const __half2*)&v1;
                a0 = __hfma2(kh[0], vh0[0], a0);
                a1 = __hfma2(kh[1], vh0[1], a1);
                a2 = __hfma2(kh[2], vh0[2], a2);
                a3 = __hfma2(kh[3], vh0[3], a3);
                a0 = __hfma2(kh[4], vh1[0], a0);
                a1 = __hfma2(kh[5], vh1[1], a1);
                a2 = __hfma2(kh[6], vh1[2], a2);
                a3 = __hfma2(kh[7], vh1[3], a3);
            }
            float2 f0 = __half22float2(a0), f1 = __half22float2(a1);
            float2 f2 = __half22float2(a2), f3 = __half22float2(a3);
            float acc = (f0.x + f0.y) + (f1.x + f1.y) + (f2.x + f2.y) + (f3.x + f3.y);
#pragma unroll
            for (int o = 16; o; o >>= 1) acc += __shfl_xor_sync(0xffffffffu, acc, o);
            if (lane == 0)
                g_u[p][row] = __fdividef(MUV, acc * (MUV / VSCALE) + EPSV);
        }
        grid_barrier();
    }
}

// ---------------- loss = sum_ij u_i K_ij C_ij v_j,  C = -reg*ln(K) -------------
__global__ void __launch_bounds__(256) loss_kernel() {
    __shared__ float svec[NN];
    __shared__ double sred[8];
    const int c = blockIdx.x;
    const int p = blockIdx.y;
    const int tid = threadIdx.x;
    const int lane = tid & 31, w = tid >> 5;

#pragma unroll
    for (int k2 = 0; k2 < 16; k2++) {
        int j = tid + k2 * 256;
        float t = g_tp[p][0][j] + g_tp[p][1][j] + g_tp[p][2][j] + g_tp[p][3][j];
        svec[j] = MUV / (t + EPSV);
    }
    __syncthreads();

    const float4* sv4 = (const float4*)svec;
    double dacc = 0.0;
#pragma unroll
    for (int rr = 0; rr < 4; rr++) {
        int row = c * 32 + w * 4 + rr;
        const uint2* Kr = (const uint2*)(g_K8 + (size_t)p * NN * NN + (size_t)row * NN) + lane;
        float acc = 0.0f;
#pragma unroll 2
        for (int i = 0; i < 16; i++) {
            uint2 kr = __ldcs(Kr + i * 32);
            float4 v0 = sv4[(lane + i * 32) * 2];
            float4 v1 = sv4[(lane + i * 32) * 2 + 1];
            float f[8];
            dec4f(kr.x, f);
            dec4f(kr.y, f + 4);
            float vv[8] = {v0.x, v0.y, v0.z, v0.w, v1.x, v1.y, v1.z, v1.w};
#pragma unroll
            for (int j = 0; j < 8; j++) {
                float cc = -REGC * __logf(fmaxf(f[j], 1e-30f));
                acc = fmaf(f[j] * cc, vv[j], acc);
            }
        }
#pragma unroll
        for (int o = 16; o; o >>= 1) acc += __shfl_xor_sync(0xffffffffu, acc, o);
        if (lane == 0) dacc += (double)acc * (double)g_u[p][row];
    }
    if (lane == 0) sred[w] = dacc;
    __syncthreads();
    if (tid == 0) {
        double s = 0.0;
#pragma unroll
        for (int i = 0; i < 8; i++) s += sred[i];
        g_part[p * GRID_SINK + c] = s;
    }
}

// ---------------- final reduction ---------------------------------------------
__global__ void final_kernel(float* out) {
    __shared__ double sd[128];
    int t = threadIdx.x;
    double s = g_part[t] + g_part[t + 128] + g_part[t + 256];
    sd[t] = s;
    __syncthreads();
    for (int o = 64; o; o >>= 1) {
        if (t < o) sd[t] += sd[t + o];
        __syncthreads();
    }
    if (t == 0) out[0] = (float)(sd[0] / 3.0);
}

// ---------------- launch -------------------------------------------------------
extern "C" void kernel_launch(void* const* d_in, const int* in_sizes, int n_in,
                              void* d_out, int out_size) {
    const float* z0 = (const float*)d_in[0];
    const float* z1 = (const float*)d_in[1];
    const float* z2 = (const float*)d_in[2];

    rowsq_kernel<<<1536, 256>>>(z0, z1, z2);
    build_kernel<<<dim3(64, 64, 3), 256>>>(z0, z1, z2);
    sinkhorn_kernel<<<GRID_SINK, 1024>>>();
    loss_kernel<<<dim3(GRID_SINK, 3), 256>>>();
    final_kernel<<<1, 128>>>((float*)d_out);
}

// round 7
// speedup vs baseline: 1.0270x; 1.0270x over previous
#include <cuda_runtime.h>
#include <cuda_fp16.h>
#include <cuda_fp8.h>

#define NN 4096
#define DD 128
#define ITERS 100
#define GRID_SINK 128
#define EPSV 1e-8f
#define MUV (1.0f / 4096.0f)
#define REGC 0.05f
#define VSCALE 1024.0f

// ---------------- static device scratch (allocation-free rule) ----------------
__device__ __align__(256) unsigned char g_K8[3ULL * NN * NN];  // 48 MB fp8 e5m2
__device__ __align__(256) float g_u[3][NN];
__device__ __align__(256) float g_tp[3][4][NN];                // phase-A partials
__device__ __align__(256) float g_sq[3][NN];
__device__ double g_part[3 * GRID_SINK];
__device__ unsigned g_cnt = 0;
__device__ volatile unsigned g_gen = 0;

// ---------------- fp8 e5m2 helpers ---------------------------------------------
// Encode (build-time only; CVT cost irrelevant there).
__device__ __forceinline__ unsigned enc4(float a, float b, float c, float d) {
    unsigned short lo = __nv_cvt_float2_to_fp8x2(make_float2(a, b), __NV_SATFINITE, __NV_E5M2);
    unsigned short hi = __nv_cvt_float2_to_fp8x2(make_float2(c, d), __NV_SATFINITE, __NV_E5M2);
    return (unsigned)lo | ((unsigned)hi << 16);
}

// Decode: positive e5m2 byte == high byte of the half. One PRMT per half2.
__device__ __forceinline__ __half2 dec2p(unsigned x, unsigned sel) {
    unsigned t = __byte_perm(x, 0, sel);
    return *reinterpret_cast<__half2*>(&t);
}

// decode 16 fp8 (uint4) -> 8 half2, pure PRMT (ALU pipe, no CVT)
__device__ __forceinline__ void dec16(uint4 k, __half2* h) {
    h[0] = dec2p(k.x, 0x1404);
    h[1] = dec2p(k.x, 0x3424);
    h[2] = dec2p(k.y, 0x1404);
    h[3] = dec2p(k.y, 0x3424);
    h[4] = dec2p(k.z, 0x1404);
    h[5] = dec2p(k.z, 0x3424);
    h[6] = dec2p(k.w, 0x1404);
    h[7] = dec2p(k.w, 0x3424);
}

__device__ __forceinline__ void dec4f(unsigned x, float* f) {
    float2 a = __half22float2(dec2p(x, 0x1404));
    float2 b = __half22float2(dec2p(x, 0x3424));
    f[0] = a.x; f[1] = a.y; f[2] = b.x; f[3] = b.y;
}

// ---------------- grid-wide barrier -------------------------------------------
__device__ __forceinline__ void grid_barrier() {
    __syncthreads();
    if (threadIdx.x == 0) {
        __threadfence();
        unsigned gen = g_gen;
        if (atomicAdd(&g_cnt, 1u) == GRID_SINK - 1) {
            atomicExch(&g_cnt, 0u);
            __threadfence();
            g_gen = gen + 1;
        } else {
            while (g_gen == gen) { }
        }
        __threadfence();   // acquire: CCTL.IVALL flushes L1
    }
    __syncthreads();
}

// ---------------- row squared norms --------------------------------------------
__global__ void rowsq_kernel(const float* __restrict__ z0, const float* __restrict__ z1,
                             const float* __restrict__ z2) {
    int gw = (blockIdx.x * blockDim.x + threadIdx.x) >> 5;
    int lane = threadIdx.x & 31;
    int which = gw >> 12, row = gw & 4095;
    const float* src = which == 0 ? z0 : (which == 1 ? z1 : z2);
    float4 v = *(const float4*)(src + (size_t)row * DD + lane * 4);
    float s = v.x * v.x + v.y * v.y + v.z * v.z + v.w * v.w;
#pragma unroll
    for (int o = 16; o; o >>= 1) s += __shfl_xor_sync(0xffffffffu, s, o);
    if (lane == 0) g_sq[which][row] = s;
}

// ---------------- build K (fp8 e5m2) for all 3 pairs ---------------------------
__global__ void __launch_bounds__(256) build_kernel(const float* __restrict__ z0,
                                                    const float* __restrict__ z1,
                                                    const float* __restrict__ z2) {
    __shared__ float sx[64][33];
    __shared__ float sy[64][33];
    const int pa[3] = {0, 0, 1};
    const int pb[3] = {1, 2, 2};
    const float* zz[3] = {z0, z1, z2};
    const int p = blockIdx.z;
    const float* x = zz[pa[p]];
    const float* y = zz[pb[p]];

    const int tid = threadIdx.x;
    const int tx = tid & 15, ty = tid >> 4;
    const int row0 = blockIdx.y << 6, col0 = blockIdx.x << 6;

    float acc[4][4] = {};

    for (int kc = 0; kc < DD; kc += 32) {
        __syncthreads();
#pragma unroll
        for (int q = 0; q < 2; q++) {
            int idx = tid + (q << 8);
            int r = idx >> 3, kk = (idx & 7) << 2;
            float4 a = *(const float4*)(x + (size_t)(row0 + r) * DD + kc + kk);
            sx[r][kk] = a.x; sx[r][kk + 1] = a.y; sx[r][kk + 2] = a.z; sx[r][kk + 3] = a.w;
            float4 b = *(const float4*)(y + (size_t)(col0 + r) * DD + kc + kk);
            sy[r][kk] = b.x; sy[r][kk + 1] = b.y; sy[r][kk + 2] = b.z; sy[r][kk + 3] = b.w;
        }
        __syncthreads();
#pragma unroll
        for (int k = 0; k < 32; k++) {
            float xa[4], yb[4];
#pragma unroll
            for (int a = 0; a < 4; a++) xa[a] = sx[ty * 4 + a][k];
#pragma unroll
            for (int b = 0; b < 4; b++) yb[b] = sy[tx * 4 + b][k];
#pragma unroll
            for (int a = 0; a < 4; a++)
#pragma unroll
                for (int b = 0; b < 4; b++)
                    acc[a][b] = fmaf(xa[a], yb[b], acc[a][b]);
        }
    }

    float xs[4], ys[4];
#pragma unroll
    for (int a = 0; a < 4; a++) xs[a] = g_sq[pa[p]][row0 + ty * 4 + a];
#pragma unroll
    for (int b = 0; b < 4; b++) ys[b] = g_sq[pb[p]][col0 + tx * 4 + b];

    const size_t base = (size_t)p * NN * NN;
#pragma unroll
    for (int a = 0; a < 4; a++) {
        size_t off = base + (size_t)(row0 + ty * 4 + a) * NN + col0 + tx * 4;
        float kk[4];
#pragma unroll
        for (int b = 0; b < 4; b++) {
            float c = fmaxf(xs[a] + ys[b] - 2.0f * acc[a][b], 0.0f);
            kk[b] = fmaxf(__expf(-20.0f * c), 0.002f);   // clamp above fp8 underflow
        }
        *(unsigned*)(g_K8 + off) = enc4(kk[0], kk[1], kk[2], kk[3]);
    }
}

// ---------------- persistent fused 3-pair Sinkhorn (fp8 K, half2 math) ---------
__global__ void __launch_bounds__(512, 1) sinkhorn_kernel() {
    __shared__ __align__(16) unsigned char smem_raw[16384];
    __half2* svu = (__half2*)smem_raw;                 // phase A: u bcast [1024] (4KB)
    float* red = (float*)(smem_raw + 4096);            // phase A: [16][128] (8KB)
    __half* svh = (__half*)smem_raw;                   // phase B: v'' [4096] (8KB)

    const int c = blockIdx.x;
    const int tid = threadIdx.x;
    const int lane = tid & 31, w = tid >> 5;           // 16 warps
    const int rb = c >> 5, cb = c & 31;                // phase-A tile: 1024 rows x 128 cols
    const int cg = lane & 7, ro = lane >> 3;           // col-group, row-offset

    if (tid < 32) {
#pragma unroll
        for (int p = 0; p < 3; p++) g_u[p][c * 32 + tid] = 1.0f;
    }
    grid_barrier();

    for (int it = 0; it < ITERS; it++) {
        // ================= Phase A: partial t = K^T u =========================
#pragma unroll 1
        for (int p = 0; p < 3; p++) {
            __syncthreads();
            svu[tid]       = __float2half2_rn(g_u[p][rb * 1024 + tid]);
            svu[tid + 512] = __float2half2_rn(g_u[p][rb * 1024 + tid + 512]);
            __syncthreads();

            const uint4* Ka = (const uint4*)(g_K8 + (size_t)p * NN * NN +
                                             (size_t)(rb * 1024 + w * 64 + ro) * NN +
                                             cb * 128 + cg * 16);
            float t[16];
            __half2 acc[8];
#pragma unroll
            for (int j = 0; j < 8; j++) acc[j] = __half2half2(__ushort_as_half(0));
#pragma unroll
            for (int k = 0; k < 16; k++) t[k] = 0.0f;

#pragma unroll
            for (int i = 0; i < 16; i++) {
                uint4 kr = __ldcg(Ka + (size_t)i * 1024);   // +4 rows
                __half2 uu = svu[w * 64 + i * 4 + ro];
                __half2 kh[8];
                dec16(kr, kh);
#pragma unroll
                for (int j = 0; j < 8; j++) acc[j] = __hfma2(kh[j], uu, acc[j]);
                if (i == 7 || i == 15) {
#pragma unroll
                    for (int j = 0; j < 8; j++) {
                        float2 f = __half22float2(acc[j]);
                        t[j * 2] += f.x;
                        t[j * 2 + 1] += f.y;
                        acc[j] = __half2half2(__ushort_as_half(0));
                    }
                }
            }
            // reduce over ro (lane bits 3,4)
#pragma unroll
            for (int k = 0; k < 16; k++) {
                t[k] += __shfl_xor_sync(0xffffffffu, t[k], 8);
                t[k] += __shfl_xor_sync(0xffffffffu, t[k], 16);
            }
            if (ro == 0) {
#pragma unroll
                for (int k = 0; k < 16; k++) red[w * 128 + cg * 16 + k] = t[k];
            }
            __syncthreads();
            if (tid < 128) {
                float s = red[tid];
#pragma unroll
                for (int w2 = 1; w2 < 16; w2++) s += red[w2 * 128 + tid];
                g_tp[p][rb][cb * 128 + tid] = s;
            }
        }
        grid_barrier();

        // ================= Phase B: u = mu / (K v + eps) ======================
#pragma unroll 1
        for (int p = 0; p < 3; p++) {
            __syncthreads();
            {   // stage v'' = VSCALE/(t+eps) as half[4096]
                const float4* tp0 = (const float4*)g_tp[p][0];
                const float4* tp1 = (const float4*)g_tp[p][1];
                const float4* tp2 = (const float4*)g_tp[p][2];
                const float4* tp3 = (const float4*)g_tp[p][3];
                int a = tid * 2, b = tid * 2 + 1;
                float4 A0 = tp0[a], A1 = tp1[a], A2 = tp2[a], A3 = tp3[a];
                float4 B0 = tp0[b], B1 = tp1[b], B2 = tp2[b], B3 = tp3[b];
                float4 A = make_float4(A0.x + A1.x + A2.x + A3.x, A0.y + A1.y + A2.y + A3.y,
                                       A0.z + A1.z + A2.z + A3.z, A0.w + A1.w + A2.w + A3.w);
                float4 B = make_float4(B0.x + B1.x + B2.x + B3.x, B0.y + B1.y + B2.y + B3.y,
                                       B0.z + B1.z + B2.z + B3.z, B0.w + B1.w + B2.w + B3.w);
                __half2 h0 = __floats2half2_rn(__fdividef(VSCALE, A.x + EPSV),
                                               __fdividef(VSCALE, A.y + EPSV));
                __half2 h1 = __floats2half2_rn(__fdividef(VSCALE, A.z + EPSV),
                                               __fdividef(VSCALE, A.w + EPSV));
                __half2 h2 = __floats2half2_rn(__fdividef(VSCALE, B.x + EPSV),
                                               __fdividef(VSCALE, B.y + EPSV));
                __half2 h3 = __floats2half2_rn(__fdividef(VSCALE, B.z + EPSV),
                                               __fdividef(VSCALE, B.w + EPSV));
                uint4 pk;
                pk.x = *reinterpret_cast<unsigned*>(&h0);
                pk.y = *reinterpret_cast<unsigned*>(&h1);
                pk.z = *reinterpret_cast<unsigned*>(&h2);
                pk.w = *reinterpret_cast<unsigned*>(&h3);
                ((uint4*)svh)[tid] = pk;
            }
            __syncthreads();

            const uint4* sv4 = (const uint4*)svh;
#pragma unroll
            for (int r = 0; r < 2; r++) {
                int row = c * 32 + w * 2 + r;
                const uint4* Kr = (const uint4*)(g_K8 + (size_t)p * NN * NN +
                                                 (size_t)row * NN) + lane;
                __half2 a0 = __half2half2(__ushort_as_half(0));
                __half2 a1 = a0, a2 = a0, a3 = a0;
#pragma unroll
                for (int i = 0; i < 8; i++) {
                    uint4 kr = __ldcg(Kr + i * 32);
                    uint4 v0 = sv4[i * 64 + lane * 2];
                    uint4 v1 = sv4[i * 64 + lane * 2 + 1];
                    __half2 kh[8];
                    dec16(kr, kh);
                    const __half2* vh0 = (const __half2*)&v0;
                    const __half2* vh1 = (const __half2*)&v1;
                    a0 = __hfma2(kh[0], vh0[0], a0);
                    a1 = __hfma2(kh[1], vh0[1], a1);
                    a2 = __hfma2(kh[2], vh0[2], a2);
                    a3 = __hfma2(kh[3], vh0[3], a3);
                    a0 = __hfma2(kh[4], vh1[0], a0);
                    a1 = __hfma2(kh[5], vh1[1], a1);
                    a2 = __hfma2(kh[6], vh1[2], a2);
                    a3 = __hfma2(kh[7], vh1[3], a3);
                }
                float2 f0 = __half22float2(a0), f1 = __half22float2(a1);
                float2 f2 = __half22float2(a2), f3 = __half22float2(a3);
                float acc = (f0.x + f0.y) + (f1.x + f1.y) + (f2.x + f2.y) + (f3.x + f3.y);
#pragma unroll
                for (int o = 16; o; o >>= 1) acc += __shfl_xor_sync(0xffffffffu, acc, o);
                if (lane == 0)
                    g_u[p][row] = __fdividef(MUV, acc * (MUV / VSCALE) + EPSV);
            }
        }
        grid_barrier();
    }
}

// ---------------- loss = sum_ij u_i K_ij C_ij v_j,  C = -reg*ln(K) -------------
__global__ void __launch_bounds__(256) loss_kernel() {
    __shared__ float svec[NN];
    __shared__ double sred[8];
    const int c = blockIdx.x;
    const int p = blockIdx.y;
    const int tid = threadIdx.x;
    const int lane = tid & 31, w = tid >> 5;

#pragma unroll
    for (int k2 = 0; k2 < 16; k2++) {
        int j = tid + k2 * 256;
        float t = g_tp[p][0][j] + g_tp[p][1][j] + g_tp[p][2][j] + g_tp[p][3][j];
        svec[j] = MUV / (t + EPSV);
    }
    __syncthreads();

    const float4* sv4 = (const float4*)svec;
    double dacc = 0.0;
#pragma unroll
    for (int rr = 0; rr < 4; rr++) {
        int row = c * 32 + w * 4 + rr;
        const uint2* Kr = (const uint2*)(g_K8 + (size_t)p * NN * NN + (size_t)row * NN) + lane;
        float acc = 0.0f;
#pragma unroll 2
        for (int i = 0; i < 16; i++) {
            uint2 kr = __ldcs(Kr + i * 32);
            float4 v0 = sv4[(lane + i * 32) * 2];
            float4 v1 = sv4[(lane + i * 32) * 2 + 1];
            float f[8];
            dec4f(kr.x, f);
            dec4f(kr.y, f + 4);
            float vv[8] = {v0.x, v0.y, v0.z, v0.w, v1.x, v1.y, v1.z, v1.w};
#pragma unroll
            for (int j = 0; j < 8; j++) {
                float cc = -REGC * __logf(fmaxf(f[j], 1e-30f));
                acc = fmaf(f[j] * cc, vv[j], acc);
            }
        }
#pragma unroll
        for (int o = 16; o; o >>= 1) acc += __shfl_xor_sync(0xffffffffu, acc, o);
        if (lane == 0) dacc += (double)acc * (double)g_u[p][row];
    }
    if (lane == 0) sred[w] = dacc;
    __syncthreads();
    if (tid == 0) {
        double s = 0.0;
#pragma unroll
        for (int i = 0; i < 8; i++) s += sred[i];
        g_part[p * GRID_SINK + c] = s;
    }
}

// ---------------- final reduction ---------------------------------------------
__global__ void final_kernel(float* out) {
    __shared__ double sd[128];
    int t = threadIdx.x;
    double s = g_part[t] + g_part[t + 128] + g_part[t + 256];
    sd[t] = s;
    __syncthreads();
    for (int o = 64; o; o >>= 1) {
        if (t < o) sd[t] += sd[t + o];
        __syncthreads();
    }
    if (t == 0) out[0] = (float)(sd[0] / 3.0);
}

// ---------------- launch -------------------------------------------------------
extern "C" void kernel_launch(void* const* d_in, const int* in_sizes, int n_in,
                              void* d_out, int out_size) {
    const float* z0 = (const float*)d_in[0];
    const float* z1 = (const float*)d_in[1];
    const float* z2 = (const float*)d_in[2];

    rowsq_kernel<<<1536, 256>>>(z0, z1, z2);
    build_kernel<<<dim3(64, 64, 3), 256>>>(z0, z1, z2);
    sinkhorn_kernel<<<GRID_SINK, 512>>>();
    loss_kernel<<<dim3(GRID_SINK, 3), 256>>>();
    final_kernel<<<1, 128>>>((float*)d_out);
}

// round 8
// speedup vs baseline: 1.0906x; 1.0619x over previous
#include <cuda_runtime.h>
#include <cuda_fp16.h>
#include <cuda_fp8.h>

#define NN 4096
#define DD 128
#define ITERS 100
#define GRID_SINK 128
#define EPSV 1e-8f
#define MUV (1.0f / 4096.0f)
#define REGC 0.05f
#define USF 4096.0f           // u staging scale
#define VS2 1048576.0f        // v storage scale (2^20)

// ---------------- static device scratch (allocation-free rule) ----------------
__device__ __align__(256) unsigned char g_K8[3ULL * NN * NN];  // 48 MB fp8 e4m3
__device__ __align__(256) float g_u[3][NN];                    // true u
__device__ __align__(256) float g_vs[3][NN];                   // v * VS2
__device__ __align__(256) float g_tau[3][GRID_SINK][NN];       // outer-product partials (6MB)
__device__ __align__(256) float g_sq[3][NN];
__device__ double g_part[3 * GRID_SINK];
__device__ unsigned g_cnt = 0;
__device__ volatile unsigned g_gen = 0;

// ---------------- fp8 e4m3 helpers ---------------------------------------------
__device__ __forceinline__ unsigned enc4(float a, float b, float c, float d) {
    unsigned short lo = __nv_cvt_float2_to_fp8x2(make_float2(a, b), __NV_SATFINITE, __NV_E4M3);
    unsigned short hi = __nv_cvt_float2_to_fp8x2(make_float2(c, d), __NV_SATFINITE, __NV_E4M3);
    return (unsigned)lo | ((unsigned)hi << 16);
}

__device__ __forceinline__ __half2 dec2h(unsigned short s) {
    __half2_raw r = __nv_cvt_fp8x2_to_halfraw2((__nv_fp8x2_storage_t)s, __NV_E4M3);
    return *reinterpret_cast<__half2*>(&r);
}

__device__ __forceinline__ void dec16(uint4 k, __half2* h) {
    h[0] = dec2h((unsigned short)(k.x & 0xFFFFu));
    h[1] = dec2h((unsigned short)(k.x >> 16));
    h[2] = dec2h((unsigned short)(k.y & 0xFFFFu));
    h[3] = dec2h((unsigned short)(k.y >> 16));
    h[4] = dec2h((unsigned short)(k.z & 0xFFFFu));
    h[5] = dec2h((unsigned short)(k.z >> 16));
    h[6] = dec2h((unsigned short)(k.w & 0xFFFFu));
    h[7] = dec2h((unsigned short)(k.w >> 16));
}

__device__ __forceinline__ void dec4f(unsigned x, float* f) {
    float2 a = __half22float2(dec2h((unsigned short)(x & 0xFFFFu)));
    float2 b = __half22float2(dec2h((unsigned short)(x >> 16)));
    f[0] = a.x; f[1] = a.y; f[2] = b.x; f[3] = b.y;
}

// ---------------- grid-wide barrier -------------------------------------------
__device__ __forceinline__ void grid_barrier() {
    __syncthreads();
    if (threadIdx.x == 0) {
        __threadfence();
        unsigned gen = g_gen;
        if (atomicAdd(&g_cnt, 1u) == GRID_SINK - 1) {
            atomicExch(&g_cnt, 0u);
            __threadfence();
            g_gen = gen + 1;
        } else {
            while (g_gen == gen) { }
        }
        __threadfence();   // acquire: CCTL.IVALL flushes L1
    }
    __syncthreads();
}

// ---------------- row squared norms --------------------------------------------
__global__ void rowsq_kernel(const float* __restrict__ z0, const float* __restrict__ z1,
                             const float* __restrict__ z2) {
    int gw = (blockIdx.x * blockDim.x + threadIdx.x) >> 5;
    int lane = threadIdx.x & 31;
    int which = gw >> 12, row = gw & 4095;
    const float* src = which == 0 ? z0 : (which == 1 ? z1 : z2);
    float4 v = *(const float4*)(src + (size_t)row * DD + lane * 4);
    float s = v.x * v.x + v.y * v.y + v.z * v.z + v.w * v.w;
#pragma unroll
    for (int o = 16; o; o >>= 1) s += __shfl_xor_sync(0xffffffffu, s, o);
    if (lane == 0) g_sq[which][row] = s;
}

// ---------------- build K (fp8 e4m3) for all 3 pairs ---------------------------
__global__ void __launch_bounds__(256) build_kernel(const float* __restrict__ z0,
                                                    const float* __restrict__ z1,
                                                    const float* __restrict__ z2) {
    __shared__ float sx[64][33];
    __shared__ float sy[64][33];
    const int pa[3] = {0, 0, 1};
    const int pb[3] = {1, 2, 2};
    const float* zz[3] = {z0, z1, z2};
    const int p = blockIdx.z;
    const float* x = zz[pa[p]];
    const float* y = zz[pb[p]];

    const int tid = threadIdx.x;
    const int tx = tid & 15, ty = tid >> 4;
    const int row0 = blockIdx.y << 6, col0 = blockIdx.x << 6;

    float acc[4][4] = {};

    for (int kc = 0; kc < DD; kc += 32) {
        __syncthreads();
#pragma unroll
        for (int q = 0; q < 2; q++) {
            int idx = tid + (q << 8);
            int r = idx >> 3, kk = (idx & 7) << 2;
            float4 a = *(const float4*)(x + (size_t)(row0 + r) * DD + kc + kk);
            sx[r][kk] = a.x; sx[r][kk + 1] = a.y; sx[r][kk + 2] = a.z; sx[r][kk + 3] = a.w;
            float4 b = *(const float4*)(y + (size_t)(col0 + r) * DD + kc + kk);
            sy[r][kk] = b.x; sy[r][kk + 1] = b.y; sy[r][kk + 2] = b.z; sy[r][kk + 3] = b.w;
        }
        __syncthreads();
#pragma unroll
        for (int k = 0; k < 32; k++) {
            float xa[4], yb[4];
#pragma unroll
            for (int a = 0; a < 4; a++) xa[a] = sx[ty * 4 + a][k];
#pragma unroll
            for (int b = 0; b < 4; b++) yb[b] = sy[tx * 4 + b][k];
#pragma unroll
            for (int a = 0; a < 4; a++)
#pragma unroll
                for (int b = 0; b < 4; b++)
                    acc[a][b] = fmaf(xa[a], yb[b], acc[a][b]);
        }
    }

    float xs[4], ys[4];
#pragma unroll
    for (int a = 0; a < 4; a++) xs[a] = g_sq[pa[p]][row0 + ty * 4 + a];
#pragma unroll
    for (int b = 0; b < 4; b++) ys[b] = g_sq[pb[p]][col0 + tx * 4 + b];

    const size_t base = (size_t)p * NN * NN;
#pragma unroll
    for (int a = 0; a < 4; a++) {
        size_t off = base + (size_t)(row0 + ty * 4 + a) * NN + col0 + tx * 4;
        float kk[4];
#pragma unroll
        for (int b = 0; b < 4; b++) {
            float c = fmaxf(xs[a] + ys[b] - 2.0f * acc[a][b], 0.0f);
            kk[b] = fmaxf(__expf(-20.0f * c), 0.002f);   // clamp above fp8 underflow
        }
        *(unsigned*)(g_K8 + off) = enc4(kk[0], kk[1], kk[2], kk[3]);
    }
}

// ---------------- persistent fused 3-pair Sinkhorn (row-ownership) -------------
// CTA c owns rows [c*32, c*32+32) for all pairs. Per iteration:
//   C: u_i = mu/(K[i,:].v)   (row stream, fills L1)
//   A: tau_c[j] += K[i][j]*u_i over my rows  (same K block, L1 hits)
//   B: reduce 128 partials -> v
__global__ void __launch_bounds__(512, 1) sinkhorn_kernel() {
    __shared__ float su[32];                        // u*USF for my rows
    __shared__ __align__(16) __half svs[NN];        // staged v'' (8 KB)
    __shared__ float sred[12][32];
    const int c = blockIdx.x;
    const int tid = threadIdx.x;
    const int lane = tid & 31, w = tid >> 5;        // 16 warps

    // ---------- A-step: outer-product partials for my 32 rows -----------------
    auto outerA = [&](int p) {
        const unsigned char* Kb = g_K8 + (size_t)p * NN * NN +
                                  (size_t)(c * 32) * NN + w * 256 + lane * 8;
        float acc[8] = {};
#pragma unroll
        for (int r = 0; r < 32; r += 2) {
            uint2 k0 = *(const uint2*)(Kb + (size_t)r * NN);         // L1 hit after C
            uint2 k1 = *(const uint2*)(Kb + (size_t)(r + 1) * NN);
            float f0[8], f1[8];
            dec4f(k0.x, f0); dec4f(k0.y, f0 + 4);
            dec4f(k1.x, f1); dec4f(k1.y, f1 + 4);
            float u0 = su[r], u1 = su[r + 1];
#pragma unroll
            for (int j = 0; j < 8; j++)
                acc[j] = fmaf(f0[j], u0, fmaf(f1[j], u1, acc[j]));
        }
        float* tp = &g_tau[p][c][w * 256 + lane * 8];
        *(float4*)tp = make_float4(acc[0], acc[1], acc[2], acc[3]);
        *(float4*)(tp + 4) = make_float4(acc[4], acc[5], acc[6], acc[7]);
    };

    // ---------- B-step: reduce partials -> v'' --------------------------------
    auto phaseB = [&]() {
        if (w < 12) {
            int pb = w >> 2, q = w & 3;
            const float* tp = &g_tau[pb][q * 32][c * 32 + lane];
            float s = 0.0f;
#pragma unroll
            for (int cc = 0; cc < 32; cc++) s += __ldcg(tp + (size_t)cc * NN);
            sred[w][lane] = s;
        }
        __syncthreads();
        if (tid < 96) {
            int pb = tid >> 5, j = tid & 31;
            float tauS = sred[pb * 4][j] + sred[pb * 4 + 1][j] +
                         sred[pb * 4 + 2][j] + sred[pb * 4 + 3][j];
            float tau = tauS * (1.0f / USF);            // true Kt.u
            g_vs[pb][c * 32 + j] = (VS2 * MUV) / (tau + EPSV);
        }
    };

    // ---------- initial A0 with u = 1 -----------------------------------------
    if (tid < 32) su[tid] = USF;
    __syncthreads();
#pragma unroll 1
    for (int p = 0; p < 3; p++) outerA(p);
    grid_barrier();
    phaseB();
    grid_barrier();

    for (int t = 1; t <= ITERS; t++) {
#pragma unroll 1
        for (int p = 0; p < 3; p++) {
            // stage v'' as half
            {
                const float4* gv = (const float4*)g_vs[p];
                float4 x0 = __ldcg(gv + tid * 2);
                float4 x1 = __ldcg(gv + tid * 2 + 1);
                __half2 h0 = __floats2half2_rn(x0.x, x0.y);
                __half2 h1 = __floats2half2_rn(x0.z, x0.w);
                __half2 h2 = __floats2half2_rn(x1.x, x1.y);
                __half2 h3 = __floats2half2_rn(x1.z, x1.w);
                uint4 pk;
                pk.x = *reinterpret_cast<unsigned*>(&h0);
                pk.y = *reinterpret_cast<unsigned*>(&h1);
                pk.z = *reinterpret_cast<unsigned*>(&h2);
                pk.w = *reinterpret_cast<unsigned*>(&h3);
                ((uint4*)svs)[tid] = pk;
            }
            __syncthreads();

            // C-step: 2 rows per warp, shared v loads, K via default (L1-fill)
            {
                int r0 = c * 32 + w * 2;
                const uint4* K0 = (const uint4*)(g_K8 + (size_t)p * NN * NN +
                                                 (size_t)r0 * NN);
                const uint4* K1 = K0 + NN / 16;
                const uint4* sv4 = (const uint4*)svs;
                __half2 z = __half2half2(__ushort_as_half(0));
                __half2 a0 = z, a1 = z, a2 = z, a3 = z;
                __half2 b0 = z, b1 = z, b2 = z, b3 = z;
#pragma unroll
                for (int i = 0; i < 8; i++) {
                    uint4 kr0 = K0[lane + i * 32];          // plain load -> L1
                    uint4 kr1 = K1[lane + i * 32];
                    uint4 v0 = sv4[i * 64 + lane * 2];
                    uint4 v1 = sv4[i * 64 + lane * 2 + 1];
                    __half2 kh0[8], kh1[8];
                    dec16(kr0, kh0);
                    dec16(kr1, kh1);
                    const __half2* vh0 = (const __half2*)&v0;
                    const __half2* vh1 = (const __half2*)&v1;
                    a0 = __hfma2(kh0[0], vh0[0], a0);
                    a1 = __hfma2(kh0[1], vh0[1], a1);
                    a2 = __hfma2(kh0[2], vh0[2], a2);
                    a3 = __hfma2(kh0[3], vh0[3], a3);
                    a0 = __hfma2(kh0[4], vh1[0], a0);
                    a1 = __hfma2(kh0[5], vh1[1], a1);
                    a2 = __hfma2(kh0[6], vh1[2], a2);
                    a3 = __hfma2(kh0[7], vh1[3], a3);
                    b0 = __hfma2(kh1[0], vh0[0], b0);
                    b1 = __hfma2(kh1[1], vh0[1], b1);
                    b2 = __hfma2(kh1[2], vh0[2], b2);
                    b3 = __hfma2(kh1[3], vh0[3], b3);
                    b0 = __hfma2(kh1[4], vh1[0], b0);
                    b1 = __hfma2(kh1[5], vh1[1], b1);
                    b2 = __hfma2(kh1[6], vh1[2], b2);
                    b3 = __hfma2(kh1[7], vh1[3], b3);
                }
                float2 fa0 = __half22float2(a0), fa1 = __half22float2(a1);
                float2 fa2 = __half22float2(a2), fa3 = __half22float2(a3);
                float2 fb0 = __half22float2(b0), fb1 = __half22float2(b1);
                float2 fb2 = __half22float2(b2), fb3 = __half22float2(b3);
                float s0 = (fa0.x + fa0.y) + (fa1.x + fa1.y) +
                           (fa2.x + fa2.y) + (fa3.x + fa3.y);
                float s1 = (fb0.x + fb0.y) + (fb1.x + fb1.y) +
                           (fb2.x + fb2.y) + (fb3.x + fb3.y);
#pragma unroll
                for (int o = 16; o; o >>= 1) {
                    s0 += __shfl_xor_sync(0xffffffffu, s0, o);
                    s1 += __shfl_xor_sync(0xffffffffu, s1, o);
                }
                if (lane == 0) {
                    float u0 = MUV / (s0 * (1.0f / VS2) + EPSV);
                    float u1 = MUV / (s1 * (1.0f / VS2) + EPSV);
                    g_u[p][r0] = u0;
                    g_u[p][r0 + 1] = u1;
                    su[w * 2] = u0 * USF;
                    su[w * 2 + 1] = u1 * USF;
                }
            }
            __syncthreads();

            if (t < ITERS) outerA(p);   // L1-hot re-read of the same K block
        }
        if (t < ITERS) {
            grid_barrier();
            phaseB();
            grid_barrier();
        }
    }
}

// ---------------- loss = sum_ij u_i K_ij C_ij v_j,  C = -reg*ln(K) -------------
__global__ void __launch_bounds__(256) loss_kernel() {
    __shared__ float svec[NN];
    __shared__ double sred[8];
    const int c = blockIdx.x;
    const int p = blockIdx.y;
    const int tid = threadIdx.x;
    const int lane = tid & 31, w = tid >> 5;

#pragma unroll
    for (int k2 = 0; k2 < 16; k2++) {
        int j = tid + k2 * 256;
        svec[j] = g_vs[p][j] * (1.0f / VS2);    // true v
    }
    __syncthreads();

    const float4* sv4 = (const float4*)svec;
    double dacc = 0.0;
#pragma unroll
    for (int rr = 0; rr < 4; rr++) {
        int row = c * 32 + w * 4 + rr;
        const uint2* Kr = (const uint2*)(g_K8 + (size_t)p * NN * NN + (size_t)row * NN) + lane;
        float acc = 0.0f;
#pragma unroll 2
        for (int i = 0; i < 16; i++) {
            uint2 kr = __ldcs(Kr + i * 32);
            float4 v0 = sv4[(lane + i * 32) * 2];
            float4 v1 = sv4[(lane + i * 32) * 2 + 1];
            float f[8];
            dec4f(kr.x, f);
            dec4f(kr.y, f + 4);
            float vv[8] = {v0.x, v0.y, v0.z, v0.w, v1.x, v1.y, v1.z, v1.w};
#pragma unroll
            for (int j = 0; j < 8; j++) {
                float cc = -REGC * __logf(fmaxf(f[j], 1e-30f));
                acc = fmaf(f[j] * cc, vv[j], acc);
            }
        }
#pragma unroll
        for (int o = 16; o; o >>= 1) acc += __shfl_xor_sync(0xffffffffu, acc, o);
        if (lane == 0) dacc += (double)acc * (double)g_u[p][row];
    }
    if (lane == 0) sred[w] = dacc;
    __syncthreads();
    if (tid == 0) {
        double s = 0.0;
#pragma unroll
        for (int i = 0; i < 8; i++) s += sred[i];
        g_part[p * GRID_SINK + c] = s;
    }
}

// ---------------- final reduction ---------------------------------------------
__global__ void final_kernel(float* out) {
    __shared__ double sd[128];
    int t = threadIdx.x;
    double s = g_part[t] + g_part[t + 128] + g_part[t + 256];
    sd[t] = s;
    __syncthreads();
    for (int o = 64; o; o >>= 1) {
        if (t < o) sd[t] += sd[t + o];
        __syncthreads();
    }
    if (t == 0) out[0] = (float)(sd[0] / 3.0);
}

// ---------------- launch -------------------------------------------------------
extern "C" void kernel_launch(void* const* d_in, const int* in_sizes, int n_in,
                              void* d_out, int out_size) {
    const float* z0 = (const float*)d_in[0];
    const float* z1 = (const float*)d_in[1];
    const float* z2 = (const float*)d_in[2];

    rowsq_kernel<<<1536, 256>>>(z0, z1, z2);
    build_kernel<<<dim3(64, 64, 3), 256>>>(z0, z1, z2);
    sinkhorn_kernel<<<GRID_SINK, 512>>>();
    loss_kernel<<<dim3(GRID_SINK, 3), 256>>>();
    final_kernel<<<1, 128>>>((float*)d_out);
}

// round 9
// speedup vs baseline: 1.2912x; 1.1840x over previous
#include <cuda_runtime.h>
#include <cuda_fp16.h>
#include <cuda_fp8.h>

#define NN 4096
#define DD 128
#define ITERS 100
#define GRID_SINK 128
#define EPSV 1e-8f
#define MUV (1.0f / 4096.0f)
#define REGC 0.05f
#define USF 64.0f             // u staging scale (half-safe: 32*64*K<=2048)
#define VS2 1048576.0f        // v storage scale (2^20)

// ---------------- static device scratch (allocation-free rule) ----------------
__device__ __align__(256) unsigned char g_K8[3ULL * NN * NN];  // 48 MB fp8 e4m3
__device__ __align__(256) float g_u[3][NN];                    // true u
__device__ __align__(256) float g_vs[3][NN];                   // v * VS2
__device__ __align__(256) float g_tau[3][GRID_SINK][NN];       // outer-product partials
__device__ __align__(256) float g_sq[3][NN];
__device__ double g_part[3 * GRID_SINK];
__device__ unsigned g_cnt = 0;          // monotonic barrier counter (reset in final_kernel)

// ---------------- fp8 e4m3 helpers ---------------------------------------------
__device__ __forceinline__ unsigned enc4(float a, float b, float c, float d) {
    unsigned short lo = __nv_cvt_float2_to_fp8x2(make_float2(a, b), __NV_SATFINITE, __NV_E4M3);
    unsigned short hi = __nv_cvt_float2_to_fp8x2(make_float2(c, d), __NV_SATFINITE, __NV_E4M3);
    return (unsigned)lo | ((unsigned)hi << 16);
}

__device__ __forceinline__ __half2 dec2h(unsigned short s) {
    __half2_raw r = __nv_cvt_fp8x2_to_halfraw2((__nv_fp8x2_storage_t)s, __NV_E4M3);
    return *reinterpret_cast<__half2*>(&r);
}

__device__ __forceinline__ void dec16(uint4 k, __half2* h) {
    h[0] = dec2h((unsigned short)(k.x & 0xFFFFu));
    h[1] = dec2h((unsigned short)(k.x >> 16));
    h[2] = dec2h((unsigned short)(k.y & 0xFFFFu));
    h[3] = dec2h((unsigned short)(k.y >> 16));
    h[4] = dec2h((unsigned short)(k.z & 0xFFFFu));
    h[5] = dec2h((unsigned short)(k.z >> 16));
    h[6] = dec2h((unsigned short)(k.w & 0xFFFFu));
    h[7] = dec2h((unsigned short)(k.w >> 16));
}

__device__ __forceinline__ void dec8(uint2 k, __half2* h) {
    h[0] = dec2h((unsigned short)(k.x & 0xFFFFu));
    h[1] = dec2h((unsigned short)(k.x >> 16));
    h[2] = dec2h((unsigned short)(k.y & 0xFFFFu));
    h[3] = dec2h((unsigned short)(k.y >> 16));
}

__device__ __forceinline__ void dec4f(unsigned x, float* f) {
    float2 a = __half22float2(dec2h((unsigned short)(x & 0xFFFFu)));
    float2 b = __half22float2(dec2h((unsigned short)(x >> 16)));
    f[0] = a.x; f[1] = a.y; f[2] = b.x; f[3] = b.y;
}

// ---------------- grid-wide barrier (monotonic counter) ------------------------
__device__ __forceinline__ void grid_barrier_t(unsigned target) {
    __syncthreads();
    if (threadIdx.x == 0) {
        __threadfence();                       // release my stores
        atomicAdd(&g_cnt, 1u);
        while (*(volatile unsigned*)&g_cnt < target) { }
        __threadfence();                       // acquire (CCTL.IVALL: L1 flush)
    }
    __syncthreads();
}

// ---------------- row squared norms --------------------------------------------
__global__ void rowsq_kernel(const float* __restrict__ z0, const float* __restrict__ z1,
                             const float* __restrict__ z2) {
    int gw = (blockIdx.x * blockDim.x + threadIdx.x) >> 5;
    int lane = threadIdx.x & 31;
    int which = gw >> 12, row = gw & 4095;
    const float* src = which == 0 ? z0 : (which == 1 ? z1 : z2);
    float4 v = *(const float4*)(src + (size_t)row * DD + lane * 4);
    float s = v.x * v.x + v.y * v.y + v.z * v.z + v.w * v.w;
#pragma unroll
    for (int o = 16; o; o >>= 1) s += __shfl_xor_sync(0xffffffffu, s, o);
    if (lane == 0) g_sq[which][row] = s;
}

// ---------------- build K (fp8 e4m3) for all 3 pairs ---------------------------
__global__ void __launch_bounds__(256) build_kernel(const float* __restrict__ z0,
                                                    const float* __restrict__ z1,
                                                    const float* __restrict__ z2) {
    __shared__ float sx[64][33];
    __shared__ float sy[64][33];
    const int pa[3] = {0, 0, 1};
    const int pb[3] = {1, 2, 2};
    const float* zz[3] = {z0, z1, z2};
    const int p = blockIdx.z;
    const float* x = zz[pa[p]];
    const float* y = zz[pb[p]];

    const int tid = threadIdx.x;
    const int tx = tid & 15, ty = tid >> 4;
    const int row0 = blockIdx.y << 6, col0 = blockIdx.x << 6;

    float acc[4][4] = {};

    for (int kc = 0; kc < DD; kc += 32) {
        __syncthreads();
#pragma unroll
        for (int q = 0; q < 2; q++) {
            int idx = tid + (q << 8);
            int r = idx >> 3, kk = (idx & 7) << 2;
            float4 a = *(const float4*)(x + (size_t)(row0 + r) * DD + kc + kk);
            sx[r][kk] = a.x; sx[r][kk + 1] = a.y; sx[r][kk + 2] = a.z; sx[r][kk + 3] = a.w;
            float4 b = *(const float4*)(y + (size_t)(col0 + r) * DD + kc + kk);
            sy[r][kk] = b.x; sy[r][kk + 1] = b.y; sy[r][kk + 2] = b.z; sy[r][kk + 3] = b.w;
        }
        __syncthreads();
#pragma unroll
        for (int k = 0; k < 32; k++) {
            float xa[4], yb[4];
#pragma unroll
            for (int a = 0; a < 4; a++) xa[a] = sx[ty * 4 + a][k];
#pragma unroll
            for (int b = 0; b < 4; b++) yb[b] = sy[tx * 4 + b][k];
#pragma unroll
            for (int a = 0; a < 4; a++)
#pragma unroll
                for (int b = 0; b < 4; b++)
                    acc[a][b] = fmaf(xa[a], yb[b], acc[a][b]);
        }
    }

    float xs[4], ys[4];
#pragma unroll
    for (int a = 0; a < 4; a++) xs[a] = g_sq[pa[p]][row0 + ty * 4 + a];
#pragma unroll
    for (int b = 0; b < 4; b++) ys[b] = g_sq[pb[p]][col0 + tx * 4 + b];

    const size_t base = (size_t)p * NN * NN;
#pragma unroll
    for (int a = 0; a < 4; a++) {
        size_t off = base + (size_t)(row0 + ty * 4 + a) * NN + col0 + tx * 4;
        float kk[4];
#pragma unroll
        for (int b = 0; b < 4; b++) {
            float c = fmaxf(xs[a] + ys[b] - 2.0f * acc[a][b], 0.0f);
            kk[b] = fmaxf(__expf(-20.0f * c), 0.002f);   // clamp above fp8 underflow
        }
        *(unsigned*)(g_K8 + off) = enc4(kk[0], kk[1], kk[2], kk[3]);
    }
}

// ---------------- persistent fused 3-pair Sinkhorn (row-ownership) -------------
__global__ void __launch_bounds__(512, 1) sinkhorn_kernel() {
    __shared__ __half su_h[32];                     // u*USF (half) for my rows
    __shared__ __align__(16) __half svs[NN];        // staged v'' (8 KB)
    __shared__ float sred[12][32];
    const int c = blockIdx.x;
    const int tid = threadIdx.x;
    const int lane = tid & 31, w = tid >> 5;        // 16 warps
    unsigned nb = 0;                                 // barrier index

    // ---------- A-step: half2 outer-product partials for my 32 rows -----------
    auto outerA = [&](int p) {
        const unsigned char* Kb = g_K8 + (size_t)p * NN * NN +
                                  (size_t)(c * 32) * NN + w * 256 + lane * 8;
        __half2 z = __half2half2(__ushort_as_half(0));
        __half2 acc2[4] = {z, z, z, z};
#pragma unroll
        for (int r = 0; r < 32; r += 2) {
            uint2 k0 = *(const uint2*)(Kb + (size_t)r * NN);       // L1 hit after C
            uint2 k1 = *(const uint2*)(Kb + (size_t)(r + 1) * NN);
            __half2 u0 = __half2half2(su_h[r]);
            __half2 u1 = __half2half2(su_h[r + 1]);
            __half2 h0[4], h1[4];
            dec8(k0, h0);
            dec8(k1, h1);
#pragma unroll
            for (int q = 0; q < 4; q++)
                acc2[q] = __hfma2(h0[q], u0, __hfma2(h1[q], u1, acc2[q]));
        }
        float2 f0 = __half22float2(acc2[0]), f1 = __half22float2(acc2[1]);
        float2 f2 = __half22float2(acc2[2]), f3 = __half22float2(acc2[3]);
        float* tp = &g_tau[p][c][w * 256 + lane * 8];
        *(float4*)tp = make_float4(f0.x, f0.y, f1.x, f1.y);
        *(float4*)(tp + 4) = make_float4(f2.x, f2.y, f3.x, f3.y);
    };

    // ---------- B-step: reduce partials -> v'' --------------------------------
    auto phaseB = [&]() {
        if (w < 12) {
            int pb = w >> 2, q = w & 3;
            const float* tp = &g_tau[pb][q * 32][c * 32 + lane];
            float s = 0.0f;
#pragma unroll
            for (int cc = 0; cc < 32; cc++) s += __ldcg(tp + (size_t)cc * NN);
            sred[w][lane] = s;
        }
        __syncthreads();
        if (tid < 96) {
            int pb = tid >> 5, j = tid & 31;
            float tauS = sred[pb * 4][j] + sred[pb * 4 + 1][j] +
                         sred[pb * 4 + 2][j] + sred[pb * 4 + 3][j];
            float tau = tauS * (1.0f / USF);            // true Kt.u
            g_vs[pb][c * 32 + j] = (VS2 * MUV) / (tau + EPSV);
        }
    };

    // ---------- initial A0 with u = 1 -----------------------------------------
    if (tid < 32) su_h[tid] = __float2half_rn(USF);
    __syncthreads();
#pragma unroll 1
    for (int p = 0; p < 3; p++) outerA(p);
    grid_barrier_t(++nb * GRID_SINK);
    phaseB();
    grid_barrier_t(++nb * GRID_SINK);

    for (int t = 1; t <= ITERS; t++) {
#pragma unroll 1
        for (int p = 0; p < 3; p++) {
            // stage v'' as half
            {
                const float4* gv = (const float4*)g_vs[p];
                float4 x0 = __ldcg(gv + tid * 2);
                float4 x1 = __ldcg(gv + tid * 2 + 1);
                __half2 h0 = __floats2half2_rn(x0.x, x0.y);
                __half2 h1 = __floats2half2_rn(x0.z, x0.w);
                __half2 h2 = __floats2half2_rn(x1.x, x1.y);
                __half2 h3 = __floats2half2_rn(x1.z, x1.w);
                uint4 pk;
                pk.x = *reinterpret_cast<unsigned*>(&h0);
                pk.y = *reinterpret_cast<unsigned*>(&h1);
                pk.z = *reinterpret_cast<unsigned*>(&h2);
                pk.w = *reinterpret_cast<unsigned*>(&h3);
                ((uint4*)svs)[tid] = pk;
            }
            __syncthreads();

            // C-step: 2 rows per warp, shared v loads, K via plain loads (L1-fill)
            {
                int r0 = c * 32 + w * 2;
                const uint4* K0 = (const uint4*)(g_K8 + (size_t)p * NN * NN +
                                                 (size_t)r0 * NN);
                const uint4* K1 = K0 + NN / 16;
                const uint4* sv4 = (const uint4*)svs;
                __half2 z = __half2half2(__ushort_as_half(0));
                __half2 a0 = z, a1 = z, a2 = z, a3 = z;
                __half2 b0 = z, b1 = z, b2 = z, b3 = z;
#pragma unroll
                for (int i = 0; i < 8; i++) {
                    uint4 kr0 = K0[lane + i * 32];
                    uint4 kr1 = K1[lane + i * 32];
                    uint4 v0 = sv4[i * 64 + lane * 2];
                    uint4 v1 = sv4[i * 64 + lane * 2 + 1];
                    __half2 kh0[8], kh1[8];
                    dec16(kr0, kh0);
                    dec16(kr1, kh1);
                    const __half2* vh0 = (const __half2*)&v0;
                    const __half2* vh1 = (const __half2*)&v1;
                    a0 = __hfma2(kh0[0], vh0[0], a0);
                    a1 = __hfma2(kh0[1], vh0[1], a1);
                    a2 = __hfma2(kh0[2], vh0[2], a2);
                    a3 = __hfma2(kh0[3], vh0[3], a3);
                    a0 = __hfma2(kh0[4], vh1[0], a0);
                    a1 = __hfma2(kh0[5], vh1[1], a1);
                    a2 = __hfma2(kh0[6], vh1[2], a2);
                    a3 = __hfma2(kh0[7], vh1[3], a3);
                    b0 = __hfma2(kh1[0], vh0[0], b0);
                    b1 = __hfma2(kh1[1], vh0[1], b1);
                    b2 = __hfma2(kh1[2], vh0[2], b2);
                    b3 = __hfma2(kh1[3], vh0[3], b3);
                    b0 = __hfma2(kh1[4], vh1[0], b0);
                    b1 = __hfma2(kh1[5], vh1[1], b1);
                    b2 = __hfma2(kh1[6], vh1[2], b2);
                    b3 = __hfma2(kh1[7], vh1[3], b3);
                }
                float2 fa0 = __half22float2(a0), fa1 = __half22float2(a1);
                float2 fa2 = __half22float2(a2), fa3 = __half22float2(a3);
                float2 fb0 = __half22float2(b0), fb1 = __half22float2(b1);
                float2 fb2 = __half22float2(b2), fb3 = __half22float2(b3);
                float s0 = (fa0.x + fa0.y) + (fa1.x + fa1.y) +
                           (fa2.x + fa2.y) + (fa3.x + fa3.y);
                float s1 = (fb0.x + fb0.y) + (fb1.x + fb1.y) +
                           (fb2.x + fb2.y) + (fb3.x + fb3.y);
#pragma unroll
                for (int o = 16; o; o >>= 1) {
                    s0 += __shfl_xor_sync(0xffffffffu, s0, o);
                    s1 += __shfl_xor_sync(0xffffffffu, s1, o);
                }
                if (lane == 0) {
                    float u0 = MUV / (s0 * (1.0f / VS2) + EPSV);
                    float u1 = MUV / (s1 * (1.0f / VS2) + EPSV);
                    g_u[p][r0] = u0;
                    g_u[p][r0 + 1] = u1;
                    su_h[w * 2] = __float2half_rn(u0 * USF);
                    su_h[w * 2 + 1] = __float2half_rn(u1 * USF);
                }
            }
            __syncthreads();

            if (t < ITERS) outerA(p);   // L1-hot re-read of the same K block
        }
        if (t < ITERS) {
            grid_barrier_t(++nb * GRID_SINK);
            phaseB();
            grid_barrier_t(++nb * GRID_SINK);
        }
    }
}

// ---------------- loss = sum_ij u_i K_ij C_ij v_j,  C = -reg*ln(K) -------------
__global__ void __launch_bounds__(256) loss_kernel() {
    __shared__ float svec[NN];
    __shared__ double sred[8];
    const int c = blockIdx.x;
    const int p = blockIdx.y;
    const int tid = threadIdx.x;
    const int lane = tid & 31, w = tid >> 5;

#pragma unroll
    for (int k2 = 0; k2 < 16; k2++) {
        int j = tid + k2 * 256;
        svec[j] = g_vs[p][j] * (1.0f / VS2);    // true v
    }
    __syncthreads();

    const float4* sv4 = (const float4*)svec;
    double dacc = 0.0;
#pragma unroll
    for (int rr = 0; rr < 4; rr++) {
        int row = c * 32 + w * 4 + rr;
        const uint2* Kr = (const uint2*)(g_K8 + (size_t)p * NN * NN + (size_t)row * NN) + lane;
        float acc = 0.0f;
#pragma unroll 2
        for (int i = 0; i < 16; i++) {
            uint2 kr = __ldcs(Kr + i * 32);
            float4 v0 = sv4[(lane + i * 32) * 2];
            float4 v1 = sv4[(lane + i * 32) * 2 + 1];
            float f[8];
            dec4f(kr.x, f);
            dec4f(kr.y, f + 4);
            float vv[8] = {v0.x, v0.y, v0.z, v0.w, v1.x, v1.y, v1.z, v1.w};
#pragma unroll
            for (int j = 0; j < 8; j++) {
                float cc = -REGC * __logf(fmaxf(f[j], 1e-30f));
                acc = fmaf(f[j] * cc, vv[j], acc);
            }
        }
#pragma unroll
        for (int o = 16; o; o >>= 1) acc += __shfl_xor_sync(0xffffffffu, acc, o);
        if (lane == 0) dacc += (double)acc * (double)g_u[p][row];
    }
    if (lane == 0) sred[w] = dacc;
    __syncthreads();
    if (tid == 0) {
        double s = 0.0;
#pragma unroll
        for (int i = 0; i < 8; i++) s += sred[i];
        g_part[p * GRID_SINK + c] = s;
    }
}

// ---------------- final reduction (also resets barrier counter) ----------------
__global__ void final_kernel(float* out) {
    __shared__ double sd[128];
    int t = threadIdx.x;
    if (t == 0) g_cnt = 0u;                 // reset for next graph replay
    double s = g_part[t] + g_part[t + 128] + g_part[t + 256];
    sd[t] = s;
    __syncthreads();
    for (int o = 64; o; o >>= 1) {
        if (t < o) sd[t] += sd[t + o];
        __syncthreads();
    }
    if (t == 0) out[0] = (float)(sd[0] / 3.0);
}

// ---------------- launch -------------------------------------------------------
extern "C" void kernel_launch(void* const* d_in, const int* in_sizes, int n_in,
                              void* d_out, int out_size) {
    const float* z0 = (const float*)d_in[0];
    const float* z1 = (const float*)d_in[1];
    const float* z2 = (const float*)d_in[2];

    rowsq_kernel<<<1536, 256>>>(z0, z1, z2);
    build_kernel<<<dim3(64, 64, 3), 256>>>(z0, z1, z2);
    sinkhorn_kernel<<<GRID_SINK, 512>>>();
    loss_kernel<<<dim3(GRID_SINK, 3), 256>>>();
    final_kernel<<<1, 128>>>((float*)d_out);
}

// round 10
// speedup vs baseline: 1.3449x; 1.0416x over previous
#include <cuda_runtime.h>
#include <cuda_fp16.h>
#include <cuda_fp8.h>

#define NN 4096
#define DD 128
#define ITERS 100
#define GRID_SINK 128
#define EPSV 1e-8f
#define MUV (1.0f / 4096.0f)
#define REGC 0.05f
#define USF 64.0f             // u staging scale (half-safe: 32*64*K<=2048)
#define VS2 1048576.0f        // v storage scale (2^20)

// ---------------- static device scratch (allocation-free rule) ----------------
__device__ __align__(256) unsigned char g_K8[3ULL * NN * NN];  // 48 MB fp8 e4m3
__device__ __align__(256) float g_u[3][NN];                    // true u
__device__ __align__(256) float g_vs[3][NN];                   // v * VS2
__device__ __align__(256) float g_tau[3][GRID_SINK][NN];       // outer-product partials
__device__ __align__(256) float g_sq[3][NN];
__device__ double g_part[3 * GRID_SINK];
__device__ unsigned g_cnt = 0;          // monotonic barrier counter (reset in final_kernel)

// ---------------- fp8 e4m3 helpers ---------------------------------------------
__device__ __forceinline__ unsigned enc4(float a, float b, float c, float d) {
    unsigned short lo = __nv_cvt_float2_to_fp8x2(make_float2(a, b), __NV_SATFINITE, __NV_E4M3);
    unsigned short hi = __nv_cvt_float2_to_fp8x2(make_float2(c, d), __NV_SATFINITE, __NV_E4M3);
    return (unsigned)lo | ((unsigned)hi << 16);
}

__device__ __forceinline__ __half2 dec2h(unsigned short s) {
    __half2_raw r = __nv_cvt_fp8x2_to_halfraw2((__nv_fp8x2_storage_t)s, __NV_E4M3);
    return *reinterpret_cast<__half2*>(&r);
}

__device__ __forceinline__ void dec16(uint4 k, __half2* h) {
    h[0] = dec2h((unsigned short)(k.x & 0xFFFFu));
    h[1] = dec2h((unsigned short)(k.x >> 16));
    h[2] = dec2h((unsigned short)(k.y & 0xFFFFu));
    h[3] = dec2h((unsigned short)(k.y >> 16));
    h[4] = dec2h((unsigned short)(k.z & 0xFFFFu));
    h[5] = dec2h((unsigned short)(k.z >> 16));
    h[6] = dec2h((unsigned short)(k.w & 0xFFFFu));
    h[7] = dec2h((unsigned short)(k.w >> 16));
}

__device__ __forceinline__ void dec8(uint2 k, __half2* h) {
    h[0] = dec2h((unsigned short)(k.x & 0xFFFFu));
    h[1] = dec2h((unsigned short)(k.x >> 16));
    h[2] = dec2h((unsigned short)(k.y & 0xFFFFu));
    h[3] = dec2h((unsigned short)(k.y >> 16));
}

__device__ __forceinline__ void dec4f(unsigned x, float* f) {
    float2 a = __half22float2(dec2h((unsigned short)(x & 0xFFFFu)));
    float2 b = __half22float2(dec2h((unsigned short)(x >> 16)));
    f[0] = a.x; f[1] = a.y; f[2] = b.x; f[3] = b.y;
}

// ---------------- grid-wide barrier (monotonic counter) ------------------------
__device__ __forceinline__ void grid_barrier_t(unsigned target) {
    __syncthreads();
    if (threadIdx.x == 0) {
        __threadfence();                       // release my stores
        atomicAdd(&g_cnt, 1u);
        while (*(volatile unsigned*)&g_cnt < target) { }
        __threadfence();                       // acquire (CCTL.IVALL: L1 flush)
    }
    __syncthreads();
}

// ---------------- row squared norms --------------------------------------------
__global__ void rowsq_kernel(const float* __restrict__ z0, const float* __restrict__ z1,
                             const float* __restrict__ z2) {
    int gw = (blockIdx.x * blockDim.x + threadIdx.x) >> 5;
    int lane = threadIdx.x & 31;
    int which = gw >> 12, row = gw & 4095;
    const float* src = which == 0 ? z0 : (which == 1 ? z1 : z2);
    float4 v = *(const float4*)(src + (size_t)row * DD + lane * 4);
    float s = v.x * v.x + v.y * v.y + v.z * v.z + v.w * v.w;
#pragma unroll
    for (int o = 16; o; o >>= 1) s += __shfl_xor_sync(0xffffffffu, s, o);
    if (lane == 0) g_sq[which][row] = s;
}

// ---------------- build K (fp8 e4m3) for all 3 pairs — HFMA2 GEMM --------------
__global__ void __launch_bounds__(256) build_kernel(const float* __restrict__ z0,
                                                    const float* __restrict__ z1,
                                                    const float* __restrict__ z2) {
    __shared__ __half2 sx[64][66];   // 64 rows x 64 half2 (K=128), pad 2
    __shared__ __half2 sy[64][66];
    const int pa[3] = {0, 0, 1};
    const int pb[3] = {1, 2, 2};
    const float* zz[3] = {z0, z1, z2};
    const int p = blockIdx.z;
    const float* x = zz[pa[p]];
    const float* y = zz[pb[p]];

    const int tid = threadIdx.x;
    const int tx = tid & 15, ty = tid >> 4;
    const int row0 = blockIdx.y << 6, col0 = blockIdx.x << 6;

    // load full 64x128 fp32 tiles, convert to half2
#pragma unroll
    for (int q = 0; q < 8; q++) {
        int idx = tid + (q << 8);            // 0..2047 float4 slots
        int r = idx >> 5, k4 = idx & 31;     // 32 float4 per row
        float4 a = *(const float4*)(x + (size_t)(row0 + r) * DD + k4 * 4);
        sx[r][k4 * 2]     = __floats2half2_rn(a.x, a.y);
        sx[r][k4 * 2 + 1] = __floats2half2_rn(a.z, a.w);
        float4 b = *(const float4*)(y + (size_t)(col0 + r) * DD + k4 * 4);
        sy[r][k4 * 2]     = __floats2half2_rn(b.x, b.y);
        sy[r][k4 * 2 + 1] = __floats2half2_rn(b.z, b.w);
    }
    __syncthreads();

    __half2 z = __half2half2(__ushort_as_half(0));
    __half2 acc[4][4] = {{z, z, z, z}, {z, z, z, z}, {z, z, z, z}, {z, z, z, z}};

#pragma unroll 8
    for (int k = 0; k < 64; k++) {
        __half2 xa[4], yb[4];
#pragma unroll
        for (int a = 0; a < 4; a++) xa[a] = sx[ty * 4 + a][k];
#pragma unroll
        for (int b = 0; b < 4; b++) yb[b] = sy[tx * 4 + b][k];
#pragma unroll
        for (int a = 0; a < 4; a++)
#pragma unroll
            for (int b = 0; b < 4; b++)
                acc[a][b] = __hfma2(xa[a], yb[b], acc[a][b]);
    }

    float xs[4], ys[4];
#pragma unroll
    for (int a = 0; a < 4; a++) xs[a] = g_sq[pa[p]][row0 + ty * 4 + a];
#pragma unroll
    for (int b = 0; b < 4; b++) ys[b] = g_sq[pb[p]][col0 + tx * 4 + b];

    const size_t base = (size_t)p * NN * NN;
#pragma unroll
    for (int a = 0; a < 4; a++) {
        size_t off = base + (size_t)(row0 + ty * 4 + a) * NN + col0 + tx * 4;
        float kk[4];
#pragma unroll
        for (int b = 0; b < 4; b++) {
            float2 d = __half22float2(acc[a][b]);
            float dot = d.x + d.y;
            float c = fmaxf(xs[a] + ys[b] - 2.0f * dot, 0.0f);
            kk[b] = fmaxf(__expf(-20.0f * c), 0.002f);   // clamp above fp8 underflow
        }
        *(unsigned*)(g_K8 + off) = enc4(kk[0], kk[1], kk[2], kk[3]);
    }
}

// ---------------- persistent fused 3-pair Sinkhorn (row-ownership) -------------
__global__ void __launch_bounds__(512, 1) sinkhorn_kernel() {
    __shared__ __half su_h[32];                     // u*USF (half) for my rows
    __shared__ __align__(16) __half svs[NN];        // staged v'' (8 KB)
    __shared__ float sred[12][32];
    const int c = blockIdx.x;
    const int tid = threadIdx.x;
    const int lane = tid & 31, w = tid >> 5;        // 16 warps
    unsigned nb = 0;                                 // barrier index

    // ---------- A-step: half2 outer-product partials for my 32 rows -----------
    auto outerA = [&](int p) {
        const unsigned char* Kb = g_K8 + (size_t)p * NN * NN +
                                  (size_t)(c * 32) * NN + w * 256 + lane * 8;
        __half2 z = __half2half2(__ushort_as_half(0));
        __half2 acc2[4] = {z, z, z, z};
#pragma unroll
        for (int r = 0; r < 32; r += 2) {
            uint2 k0 = *(const uint2*)(Kb + (size_t)r * NN);       // L1 hit after C
            uint2 k1 = *(const uint2*)(Kb + (size_t)(r + 1) * NN);
            __half2 u0 = __half2half2(su_h[r]);
            __half2 u1 = __half2half2(su_h[r + 1]);
            __half2 h0[4], h1[4];
            dec8(k0, h0);
            dec8(k1, h1);
#pragma unroll
            for (int q = 0; q < 4; q++)
                acc2[q] = __hfma2(h0[q], u0, __hfma2(h1[q], u1, acc2[q]));
        }
        float2 f0 = __half22float2(acc2[0]), f1 = __half22float2(acc2[1]);
        float2 f2 = __half22float2(acc2[2]), f3 = __half22float2(acc2[3]);
        float* tp = &g_tau[p][c][w * 256 + lane * 8];
        *(float4*)tp = make_float4(f0.x, f0.y, f1.x, f1.y);
        *(float4*)(tp + 4) = make_float4(f2.x, f2.y, f3.x, f3.y);
    };

    // ---------- B-step: reduce partials -> v'' --------------------------------
    auto phaseB = [&]() {
        if (w < 12) {
            int pb = w >> 2, q = w & 3;
            const float* tp = &g_tau[pb][q * 32][c * 32 + lane];
            float s = 0.0f;
#pragma unroll
            for (int cc = 0; cc < 32; cc++) s += __ldcg(tp + (size_t)cc * NN);
            sred[w][lane] = s;
        }
        __syncthreads();
        if (tid < 96) {
            int pb = tid >> 5, j = tid & 31;
            float tauS = sred[pb * 4][j] + sred[pb * 4 + 1][j] +
                         sred[pb * 4 + 2][j] + sred[pb * 4 + 3][j];
            float tau = tauS * (1.0f / USF);            // true Kt.u
            g_vs[pb][c * 32 + j] = (VS2 * MUV) / (tau + EPSV);
        }
    };

    // ---------- initial A0 with u = 1 -----------------------------------------
    if (tid < 32) su_h[tid] = __float2half_rn(USF);
    __syncthreads();
#pragma unroll 1
    for (int p = 0; p < 3; p++) outerA(p);
    grid_barrier_t(++nb * GRID_SINK);
    phaseB();
    grid_barrier_t(++nb * GRID_SINK);

    for (int t = 1; t <= ITERS; t++) {
#pragma unroll 1
        for (int p = 0; p < 3; p++) {
            // stage v'' as half
            {
                const float4* gv = (const float4*)g_vs[p];
                float4 x0 = __ldcg(gv + tid * 2);
                float4 x1 = __ldcg(gv + tid * 2 + 1);
                __half2 h0 = __floats2half2_rn(x0.x, x0.y);
                __half2 h1 = __floats2half2_rn(x0.z, x0.w);
                __half2 h2 = __floats2half2_rn(x1.x, x1.y);
                __half2 h3 = __floats2half2_rn(x1.z, x1.w);
                uint4 pk;
                pk.x = *reinterpret_cast<unsigned*>(&h0);
                pk.y = *reinterpret_cast<unsigned*>(&h1);
                pk.z = *reinterpret_cast<unsigned*>(&h2);
                pk.w = *reinterpret_cast<unsigned*>(&h3);
                ((uint4*)svs)[tid] = pk;
            }
            __syncthreads();

            // C-step: 2 rows per warp, shared v loads, K via plain loads (L1-fill)
            {
                int r0 = c * 32 + w * 2;
                const uint4* K0 = (const uint4*)(g_K8 + (size_t)p * NN * NN +
                                                 (size_t)r0 * NN);
                const uint4* K1 = K0 + NN / 16;
                const uint4* sv4 = (const uint4*)svs;
                __half2 z = __half2half2(__ushort_as_half(0));
                __half2 a0 = z, a1 = z, a2 = z, a3 = z;
                __half2 b0 = z, b1 = z, b2 = z, b3 = z;
#pragma unroll
                for (int i = 0; i < 8; i++) {
                    uint4 kr0 = K0[lane + i * 32];
                    uint4 kr1 = K1[lane + i * 32];
                    uint4 v0 = sv4[i * 64 + lane * 2];
                    uint4 v1 = sv4[i * 64 + lane * 2 + 1];
                    __half2 kh0[8], kh1[8];
                    dec16(kr0, kh0);
                    dec16(kr1, kh1);
                    const __half2* vh0 = (const __half2*)&v0;
                    const __half2* vh1 = (const __half2*)&v1;
                    a0 = __hfma2(kh0[0], vh0[0], a0);
                    a1 = __hfma2(kh0[1], vh0[1], a1);
                    a2 = __hfma2(kh0[2], vh0[2], a2);
                    a3 = __hfma2(kh0[3], vh0[3], a3);
                    a0 = __hfma2(kh0[4], vh1[0], a0);
                    a1 = __hfma2(kh0[5], vh1[1], a1);
                    a2 = __hfma2(kh0[6], vh1[2], a2);
                    a3 = __hfma2(kh0[7], vh1[3], a3);
                    b0 = __hfma2(kh1[0], vh0[0], b0);
                    b1 = __hfma2(kh1[1], vh0[1], b1);
                    b2 = __hfma2(kh1[2], vh0[2], b2);
                    b3 = __hfma2(kh1[3], vh0[3], b3);
                    b0 = __hfma2(kh1[4], vh1[0], b0);
                    b1 = __hfma2(kh1[5], vh1[1], b1);
                    b2 = __hfma2(kh1[6], vh1[2], b2);
                    b3 = __hfma2(kh1[7], vh1[3], b3);
                }
                float2 fa0 = __half22float2(a0), fa1 = __half22float2(a1);
                float2 fa2 = __half22float2(a2), fa3 = __half22float2(a3);
                float2 fb0 = __half22float2(b0), fb1 = __half22float2(b1);
                float2 fb2 = __half22float2(b2), fb3 = __half22float2(b3);
                float s0 = (fa0.x + fa0.y) + (fa1.x + fa1.y) +
                           (fa2.x + fa2.y) + (fa3.x + fa3.y);
                float s1 = (fb0.x + fb0.y) + (fb1.x + fb1.y) +
                           (fb2.x + fb2.y) + (fb3.x + fb3.y);
#pragma unroll
                for (int o = 16; o; o >>= 1) {
                    s0 += __shfl_xor_sync(0xffffffffu, s0, o);
                    s1 += __shfl_xor_sync(0xffffffffu, s1, o);
                }
                if (lane == 0) {
                    float u0 = MUV / (s0 * (1.0f / VS2) + EPSV);
                    float u1 = MUV / (s1 * (1.0f / VS2) + EPSV);
                    g_u[p][r0] = u0;
                    g_u[p][r0 + 1] = u1;
                    su_h[w * 2] = __float2half_rn(u0 * USF);
                    su_h[w * 2 + 1] = __float2half_rn(u1 * USF);
                }
            }
            __syncthreads();

            if (t < ITERS) outerA(p);   // L1-hot re-read of the same K block
        }
        if (t < ITERS) {
            grid_barrier_t(++nb * GRID_SINK);
            phaseB();
            grid_barrier_t(++nb * GRID_SINK);
        }
    }
}

// ---------------- loss = sum_ij u_i K_ij C_ij v_j,  C = -reg*ln(K) -------------
__global__ void __launch_bounds__(256) loss_kernel() {
    __shared__ float svec[NN];
    __shared__ double sred[8];
    const int c = blockIdx.x;
    const int p = blockIdx.y;
    const int tid = threadIdx.x;
    const int lane = tid & 31, w = tid >> 5;

#pragma unroll
    for (int k2 = 0; k2 < 16; k2++) {
        int j = tid + k2 * 256;
        svec[j] = g_vs[p][j] * (1.0f / VS2);    // true v
    }
    __syncthreads();

    const float4* sv4 = (const float4*)svec;
    double dacc = 0.0;
#pragma unroll
    for (int rr = 0; rr < 4; rr++) {
        int row = c * 32 + w * 4 + rr;
        const uint2* Kr = (const uint2*)(g_K8 + (size_t)p * NN * NN + (size_t)row * NN) + lane;
        float acc = 0.0f;
#pragma unroll 2
        for (int i = 0; i < 16; i++) {
            uint2 kr = __ldcs(Kr + i * 32);
            float4 v0 = sv4[(lane + i * 32) * 2];
            float4 v1 = sv4[(lane + i * 32) * 2 + 1];
            float f[8];
            dec4f(kr.x, f);
            dec4f(kr.y, f + 4);
            float vv[8] = {v0.x, v0.y, v0.z, v0.w, v1.x, v1.y, v1.z, v1.w};
#pragma unroll
            for (int j = 0; j < 8; j++) {
                float cc = -REGC * __logf(fmaxf(f[j], 1e-30f));
                acc = fmaf(f[j] * cc, vv[j], acc);
            }
        }
#pragma unroll
        for (int o = 16; o; o >>= 1) acc += __shfl_xor_sync(0xffffffffu, acc, o);
        if (lane == 0) dacc += (double)acc * (double)g_u[p][row];
    }
    if (lane == 0) sred[w] = dacc;
    __syncthreads();
    if (tid == 0) {
        double s = 0.0;
#pragma unroll
        for (int i = 0; i < 8; i++) s += sred[i];
        g_part[p * GRID_SINK + c] = s;
    }
}

// ---------------- final reduction (also resets barrier counter) ----------------
__global__ void final_kernel(float* out) {
    __shared__ double sd[128];
    int t = threadIdx.x;
    if (t == 0) g_cnt = 0u;                 // reset for next graph replay
    double s = g_part[t] + g_part[t + 128] + g_part[t + 256];
    sd[t] = s;
    __syncthreads();
    for (int o = 64; o; o >>= 1) {
        if (t < o) sd[t] += sd[t + o];
        __syncthreads();
    }
    if (t == 0) out[0] = (float)(sd[0] / 3.0);
}

// ---------------- launch -------------------------------------------------------
extern "C" void kernel_launch(void* const* d_in, const int* in_sizes, int n_in,
                              void* d_out, int out_size) {
    const float* z0 = (const float*)d_in[0];
    const float* z1 = (const float*)d_in[1];
    const float* z2 = (const float*)d_in[2];

    rowsq_kernel<<<1536, 256>>>(z0, z1, z2);
    build_kernel<<<dim3(64, 64, 3), 256>>>(z0, z1, z2);
    sinkhorn_kernel<<<GRID_SINK, 512>>>();
    loss_kernel<<<dim3(GRID_SINK, 3), 256>>>();
    final_kernel<<<1, 128>>>((float*)d_out);
}